// round 17
// baseline (speedup 1.0000x reference)
#include <cuda_runtime.h>
#include <cuda_bf16.h>
#include <cstdint>

// Embedding gather: out[i, :] = table[indices[i], :]
// indices: int32 [819200], table: fp32 [1M, 64] (256B rows), out same rows.
// Persistent single-wave variant of the converged R12 config:
//  - grid = 148 SMs x 8 CTAs x 256 thr (exactly one wave, no wave
//    transitions -> no DRAM ramp-down/up gaps between CTA generations).
//  - each thread grid-strides over work items; per item: 8 lanes/row,
//    2x128-bit evict_last table loads per lane, 4-row unroll (8 independent
//    gathers in flight), one 256-bit .cs streaming store per row-chunk.

__device__ __forceinline__ float4 ldg_evict_last(const float4* p, unsigned long long pol) {
    float4 v;
    asm volatile("ld.global.nc.L2::cache_hint.v4.f32 {%0,%1,%2,%3}, [%4], %5;"
                 : "=f"(v.x), "=f"(v.y), "=f"(v.z), "=f"(v.w)
                 : "l"(p), "l"(pol));
    return v;
}

__device__ __forceinline__ void stcs256(void* p, const float4& a, const float4& b) {
    asm volatile("st.global.cs.v8.b32 [%0], {%1,%2,%3,%4,%5,%6,%7,%8};"
                 :: "l"(p),
                    "f"(a.x), "f"(a.y), "f"(a.z), "f"(a.w),
                    "f"(b.x), "f"(b.y), "f"(b.z), "f"(b.w)
                 : "memory");
}

__global__ void __launch_bounds__(256)
emb_gather_persist_kernel(const int* __restrict__ idx,
                          const float4* __restrict__ table,
                          char* __restrict__ out,
                          int nrows, int quarter) {
    unsigned long long pol;
    asm volatile("createpolicy.fractional.L2::evict_last.b64 %0, 1.0;" : "=l"(pol));

    int stride_items = gridDim.x * blockDim.x;             // items per sweep
    int nitems = quarter * 8;                              // row-quarters x lanes

    for (int t = blockIdx.x * blockDim.x + threadIdx.x; t < nitems; t += stride_items) {
        int row = t >> 3;          // row within first quarter
        int lane = t & 7;          // each lane owns 32B = 2 float4 slots

        int r0 = row;
        int r1 = row + quarter;
        int r2 = row + 2 * quarter;
        int r3 = row + 3 * quarter;

        int i0 = __ldg(&idx[r0]);
        int i1 = __ldg(&idx[r1]);
        int i2 = (r2 < nrows) ? __ldg(&idx[r2]) : 0;
        int i3 = (r3 < nrows) ? __ldg(&idx[r3]) : 0;

        int slot = lane * 2;       // float4 slot within the 16-slot row

        // 8 independent 128-bit random table loads in flight
        float4 a0 = ldg_evict_last(&table[(size_t)i0 * 16 + slot],     pol);
        float4 b0 = ldg_evict_last(&table[(size_t)i0 * 16 + slot + 1], pol);
        float4 a1 = ldg_evict_last(&table[(size_t)i1 * 16 + slot],     pol);
        float4 b1 = ldg_evict_last(&table[(size_t)i1 * 16 + slot + 1], pol);
        float4 a2 = ldg_evict_last(&table[(size_t)i2 * 16 + slot],     pol);
        float4 b2 = ldg_evict_last(&table[(size_t)i2 * 16 + slot + 1], pol);
        float4 a3 = ldg_evict_last(&table[(size_t)i3 * 16 + slot],     pol);
        float4 b3 = ldg_evict_last(&table[(size_t)i3 * 16 + slot + 1], pol);

        size_t off = (size_t)lane * 32;

        // 256-bit streaming stores — write-once output, don't pollute L2
        stcs256(out + (size_t)r0 * 256 + off, a0, b0);
        stcs256(out + (size_t)r1 * 256 + off, a1, b1);
        if (r2 < nrows) stcs256(out + (size_t)r2 * 256 + off, a2, b2);
        if (r3 < nrows) stcs256(out + (size_t)r3 * 256 + off, a3, b3);
    }
}

extern "C" void kernel_launch(void* const* d_in, const int* in_sizes, int n_in,
                              void* d_out, int out_size) {
    // Identify inputs by element count so ordering can't break us.
    const void* p_idx = d_in[0];
    const void* p_tab = d_in[1];
    int n_idx = in_sizes[0];
    if (n_in >= 2 && in_sizes[0] > in_sizes[1]) {
        p_tab = d_in[0];
        p_idx = d_in[1];
        n_idx = in_sizes[1];
    }

    const int*    idx = (const int*)p_idx;      // indices, int32, 819200 elems
    const float4* tab = (const float4*)p_tab;   // table, fp32 [1M,64]
    char*         out = (char*)d_out;

    int nrows = n_idx;                          // 819200
    int quarter = (nrows + 3) / 4;              // rows per unroll slot

    // Exactly one wave: 152 SMs on GB300, 8 CTAs/SM at 256 thr (occupancy
    // limit from R12 profile: occ ~86% of 2048 thr). Use 148*8 to be safe
    // across parts; grid-stride covers any remainder.
    int block = 256;
    int grid = 148 * 8;

    emb_gather_persist_kernel<<<grid, block>>>(idx, tab, out, nrows, quarter);
}